// round 11
// baseline (speedup 1.0000x reference)
#include <cuda_runtime.h>
#include <cuda_bf16.h>

#define DIM 256
#define NW 26
#define BATCH 32768

typedef unsigned long long ull;
typedef unsigned int u32;

// ---------------- device scratch (no allocs allowed) ----------------
__device__ float g_Ufp[DIM * DIM];                       // U'[n][k] fp32 (tan-form, unnormalized)
__device__ __align__(16) __nv_bfloat16 g_Uh[DIM * DIM];  // row-major [n][k]
__device__ __align__(16) __nv_bfloat16 g_Ul[DIM * DIM];

// ---------------- f32x2 helpers (build_u only) ----------------
__device__ __forceinline__ ull pk2(float lo, float hi) {
    ull r; asm("mov.b64 %0, {%1,%2};" : "=l"(r) : "f"(lo), "f"(hi)); return r;
}
__device__ __forceinline__ float lo2(ull v) {
    float a, b; asm("mov.b64 {%0,%1}, %2;" : "=f"(a), "=f"(b) : "l"(v)); return a;
}
__device__ __forceinline__ float hi2(ull v) {
    float a, b; asm("mov.b64 {%0,%1}, %2;" : "=f"(a), "=f"(b) : "l"(v)); return b;
}
__device__ __forceinline__ ull fma2(ull a, ull b, ull c) {
    ull d; asm("fma.rn.f32x2 %0, %1, %2, %3;" : "=l"(d) : "l"(a), "l"(b), "l"(c)); return d;
}
template<int M>
__device__ __forceinline__ void rot_reg(ull* u, float t) {
    ull tp = pk2(t, t), tn = pk2(-t, -t);
    #pragma unroll
    for (int k = 0; k < 32; k++) {
        if (k & M) continue;
        ull a = u[k];
        u[k]     = fma2(tn, u[k | M], a);
        u[k | M] = fma2(tp, a, u[k | M]);
    }
}
template<int LM>
__device__ __forceinline__ void rot_cross(ull* u, float t, int lane) {
    float se = (lane & LM) ? t : -t;
    ull sev = pk2(se, se);
    #pragma unroll
    for (int k = 0; k < 32; k++) {
        ull pv = __shfl_xor_sync(0xffffffffu, u[k], LM);
        u[k] = fma2(sev, pv, u[k]);
    }
}
__device__ __forceinline__ void rot_pack(ull* u, float t) {
    #pragma unroll
    for (int k = 0; k < 32; k++) {
        float lo = lo2(u[k]), hi = hi2(u[k]);
        float nl = fmaf(-t, hi, lo);
        float nh = fmaf(t, lo, hi);
        u[k] = pk2(nl, nh);
    }
}

// ---------------- kernel 1: build U' via the proven R7 circuit on basis vectors -------------
__global__ __launch_bounds__(128) void build_u_kernel(const float* __restrict__ w) {
    __shared__ float st[NW];
    int tid = threadIdx.x;
    if (tid < NW) { float s, c; sincosf(0.5f * w[tid], &s, &c); st[tid] = s / c; }
    __syncthreads();

    int lane = tid & 31, j = lane & 3;
    int warp = (blockIdx.x * blockDim.x + tid) >> 5;
    int smp = warp * 8 + (lane >> 2);                 // basis index (input k)

    ull u[32];
    #pragma unroll
    for (int f = 0; f < 16; f++) {
        int i0 = f * 16 + j * 4;
        u[2*f]   = pk2(i0 == smp ? 1.f : 0.f, i0 + 1 == smp ? 1.f : 0.f);
        u[2*f+1] = pk2(i0 + 2 == smp ? 1.f : 0.f, i0 + 3 == smp ? 1.f : 0.f);
    }
    const ull SIGN_BOTH = 0x8000000080000000ull;
    const ull SIGN_LO   = 0x0000000080000000ull;
    const ull SIGN_HI   = 0x8000000000000000ull;
    int jp = (j ^ (j >> 1)) & 1;
    ull mx0 = jp ? SIGN_LO : SIGN_HI;
    ull mx1 = jp ? SIGN_HI : SIGN_LO;

    #pragma unroll
    for (int l = 0; l < 3; l++) {
        const int b = l * 8;
        rot_cross<2>(u, st[b + 4], lane);
        rot_reg<16>(u, st[b + 0]);
        rot_cross<1>(u, st[b + 5], lane);
        rot_reg<8>(u, st[b + 1]);
        rot_pack(u, st[b + 7]);
        rot_reg<4>(u, st[b + 2]);
        rot_reg<2>(u, st[b + 3]);
        rot_reg<1>(u, st[b + 6]);
        #pragma unroll
        for (int k = 8; k < 24; k++) {
            const int rp = ((k >> 2) ^ (k >> 1) ^ k) & 1;
            u[k] ^= rp ? mx1 : mx0;
        }
        #pragma unroll
        for (int k = 24; k < 32; k++) u[k] ^= SIGN_BOTH;
    }
    rot_reg<16>(u, st[24]);
    rot_reg<8>(u, st[25]);

    #pragma unroll
    for (int k = 0; k < 32; k++) {
        int n = (k >> 1) * 16 + j * 4 + (k & 1) * 2;
        g_Ufp[n * DIM + smp]       = lo2(u[k]);
        g_Ufp[(n + 1) * DIM + smp] = hi2(u[k]);
    }
}

// ---------------- kernel 2: split U' into bf16 hi/lo (plain row-major) ----------------
__global__ __launch_bounds__(256) void split_u_kernel() {
    int t = blockIdx.x * 256 + threadIdx.x;            // 0..8191
    int base = t * 8;
    float4 v0 = *reinterpret_cast<const float4*>(&g_Ufp[base]);
    float4 v1 = *reinterpret_cast<const float4*>(&g_Ufp[base + 4]);
    float vv[8] = {v0.x, v0.y, v0.z, v0.w, v1.x, v1.y, v1.z, v1.w};
    alignas(16) __nv_bfloat16 h[8], l[8];
    #pragma unroll
    for (int e = 0; e < 8; e++) {
        h[e] = __float2bfloat16_rn(vv[e]);
        l[e] = __float2bfloat16_rn(vv[e] - __bfloat162float(h[e]));
    }
    *reinterpret_cast<uint4*>(&g_Uh[base]) = *reinterpret_cast<const uint4*>(h);
    *reinterpret_cast<uint4*>(&g_Ul[base]) = *reinterpret_cast<const uint4*>(l);
}

// ---------------- kernel 3: split-bf16 GEMM (mma.sync) + fused epilogue ----------------
// Y[m][n] = sum_k X[m][k] U'[n][k];  D = Xh*Uh + Xh*Ul + Xl*Uh  (48 k-steps of 16)
// CTA: 256 thr, tile M=128 x N=256. Warp (wm=w&3, wn=w>>2): tile 32(M) x 128(N).
#define XSTR 528                  // 256 bf16 + 16B pad, per X row
#define XS_H 0
#define XS_L 67584
#define BS0  135168
#define BSSZ 12288                // 256 n-rows x 48B (32B data + 16B pad)
#define PS   159744               // float [2][128][8]
#define SMEM_TOTAL 167936

#define LDMX4(r, addr) \
    asm volatile("ldmatrix.sync.aligned.m8n8.x4.shared.b16 {%0,%1,%2,%3}, [%4];" \
        : "=r"((r)[0]), "=r"((r)[1]), "=r"((r)[2]), "=r"((r)[3]) : "r"(addr))
#define MMA16816(d, a, b0_, b1_) \
    asm volatile("mma.sync.aligned.m16n8k16.row.col.f32.bf16.bf16.f32 " \
        "{%0,%1,%2,%3}, {%4,%5,%6,%7}, {%8,%9}, {%0,%1,%2,%3};" \
        : "+f"((d)[0]), "+f"((d)[1]), "+f"((d)[2]), "+f"((d)[3]) \
        : "r"((a)[0]), "r"((a)[1]), "r"((a)[2]), "r"((a)[3]), "r"(b0_), "r"(b1_))

__global__ __launch_bounds__(256, 1) void gemm_kernel(const float* __restrict__ x,
                                                      float* __restrict__ out) {
    extern __shared__ __align__(16) char smem[];
    u32 sb;
    asm("{ .reg .u64 t; cvta.to.shared.u64 t, %1; cvt.u32.u64 %0, t; }" : "=r"(sb) : "l"(smem));
    int tid = threadIdx.x, wid = tid >> 5, lane = tid & 31;
    int wm = wid & 3, wn = wid >> 2;
    int m0 = wm * 32, n0 = wn * 128;
    int mbase = blockIdx.x * 128;

    // ---- stage X block (128 rows): fp32 -> bf16 hi/lo in smem ----
    {
        const float4* xp = reinterpret_cast<const float4*>(x + (size_t)mbase * DIM);
        #pragma unroll
        for (int i = 0; i < 32; i++) {
            int idx = tid + i * 256;                  // 0..8191 float4s
            int row = idx >> 6, c4 = idx & 63;
            float4 v = xp[idx];
            __nv_bfloat162 h01 = __float22bfloat162_rn(make_float2(v.x, v.y));
            __nv_bfloat162 h23 = __float22bfloat162_rn(make_float2(v.z, v.w));
            float2 f01 = __bfloat1622float2(h01), f23 = __bfloat1622float2(h23);
            __nv_bfloat162 l01 = __float22bfloat162_rn(make_float2(v.x - f01.x, v.y - f01.y));
            __nv_bfloat162 l23 = __float22bfloat162_rn(make_float2(v.z - f23.x, v.w - f23.y));
            int off = row * XSTR + c4 * 8;
            *reinterpret_cast<ull*>(smem + XS_H + off) =
                ((ull)(*reinterpret_cast<u32*>(&h23)) << 32) | (*reinterpret_cast<u32*>(&h01));
            *reinterpret_cast<ull*>(smem + XS_L + off) =
                ((ull)(*reinterpret_cast<u32*>(&l23)) << 32) | (*reinterpret_cast<u32*>(&l01));
        }
    }
    // ---- load B chunk 0 (Uh, k 0..15) ----
    {
        const uint4* s = reinterpret_cast<const uint4*>(&g_Uh[tid * DIM]);
        uint4 r0 = s[0], r1 = s[1];
        *reinterpret_cast<uint4*>(smem + BS0 + tid * 48)      = r0;
        *reinterpret_cast<uint4*>(smem + BS0 + tid * 48 + 16) = r1;
    }
    __syncthreads();

    // per-lane ldmatrix address offsets
    int g = lane >> 3, ln8 = lane & 7;
    u32 aoff0 = (u32)((m0 + (g & 1) * 8 + ln8) * XSTR + (g >> 1) * 16);
    u32 aoff1 = aoff0 + 16 * XSTR;
    u32 boff  = (u32)((n0 + (g >> 1) * 8 + ln8) * 48 + (g & 1) * 16);

    float d[2][16][4];
    #pragma unroll
    for (int mt = 0; mt < 2; mt++)
        #pragma unroll
        for (int nt = 0; nt < 16; nt++)
            #pragma unroll
            for (int e = 0; e < 4; e++) d[mt][nt][e] = 0.f;

    #pragma unroll 1
    for (int s = 0; s < 48; s++) {
        int p = s >> 4;
        int kx = (s & 15) * 16;
        // prefetch next B chunk into regs
        uint4 pf0, pf1;
        if (s < 47) {
            int sn = s + 1;
            int pn = sn >> 4, kn = (sn & 15) * 16;
            const __nv_bfloat16* src = (pn == 1) ? g_Ul : g_Uh;
            const uint4* sp = reinterpret_cast<const uint4*>(&src[tid * DIM + kn]);
            pf0 = sp[0]; pf1 = sp[1];
        }
        // mma over current chunk
        u32 xbase = sb + ((p == 2) ? XS_L : XS_H) + (u32)(kx * 2);
        u32 bbase = sb + BS0 + (u32)((s & 1) * BSSZ);
        u32 a0[4], a1[4];
        LDMX4(a0, xbase + aoff0);
        LDMX4(a1, xbase + aoff1);
        #pragma unroll
        for (int tp = 0; tp < 8; tp++) {
            u32 b[4];
            LDMX4(b, bbase + boff + (u32)(tp * 16 * 48));
            MMA16816(d[0][2 * tp],     a0, b[0], b[1]);
            MMA16816(d[0][2 * tp + 1], a0, b[2], b[3]);
            MMA16816(d[1][2 * tp],     a1, b[0], b[1]);
            MMA16816(d[1][2 * tp + 1], a1, b[2], b[3]);
        }
        __syncthreads();
        if (s < 47) {
            char* dst = smem + BS0 + ((s + 1) & 1) * BSSZ + tid * 48;
            *reinterpret_cast<uint4*>(dst)      = pf0;
            *reinterpret_cast<uint4*>(dst + 16) = pf1;
            __syncthreads();
        }
    }

    // ---- fused epilogue: per-row quadratic forms ----
    // lane cols: nt*8 + (lane&3)*2 + {0,1}; col bit0 = reg parity, bit1 = lane&1.
    float* Ps = reinterpret_cast<float*>(smem + PS);   // [2][128][8]
    float sgn = (lane & 1) ? 1.f : -1.f;
    #pragma unroll
    for (int mt = 0; mt < 2; mt++) {
        #pragma unroll
        for (int h = 0; h < 2; h++) {
            float x6 = 0, x7 = 0, xx = 0, yy = 0, qa0 = 0, qa1 = 0;
            #pragma unroll
            for (int nt = 0; nt < 16; nt++) {
                float v0 = d[mt][nt][h * 2], v1 = d[mt][nt][h * 2 + 1];
                float p0 = __shfl_xor_sync(0xffffffffu, v0, 1);
                float p1 = __shfl_xor_sync(0xffffffffu, v1, 1);
                x7 = fmaf(v0, v1, x7);
                x6 = fmaf(v0, p0, x6); x6 = fmaf(v1, p1, x6);
                xx = fmaf(v0, p1, xx); xx = fmaf(v1, p0, xx);
                yy = fmaf(sgn * v0, p1, yy); yy = fmaf(-sgn * v1, p0, yy);
                qa0 = fmaf(v0, v0, qa0); qa1 = fmaf(v1, v1, qa1);
            }
            x6 += __shfl_xor_sync(0xffffffffu, x6, 2); x6 += __shfl_xor_sync(0xffffffffu, x6, 1);
            x7 += __shfl_xor_sync(0xffffffffu, x7, 2); x7 += __shfl_xor_sync(0xffffffffu, x7, 1);
            xx += __shfl_xor_sync(0xffffffffu, xx, 2); xx += __shfl_xor_sync(0xffffffffu, xx, 1);
            yy += __shfl_xor_sync(0xffffffffu, yy, 2); yy += __shfl_xor_sync(0xffffffffu, yy, 1);
            qa0 += __shfl_xor_sync(0xffffffffu, qa0, 2);
            qa1 += __shfl_xor_sync(0xffffffffu, qa1, 2);
            float pq0 = __shfl_xor_sync(0xffffffffu, qa0, 1);
            float pq1 = __shfl_xor_sync(0xffffffffu, qa1, 1);
            float q00, q01, q10, q11;
            if (!(lane & 1)) { q00 = qa0; q01 = qa1; q10 = pq0; q11 = pq1; }
            else             { q00 = pq0; q01 = pq1; q10 = qa0; q11 = qa1; }
            if (!(lane & 3)) {
                int row = m0 + mt * 16 + h * 8 + (lane >> 2);
                float* p = Ps + (wn * 128 + row) * 8;
                p[0] = x6; p[1] = x7; p[2] = xx; p[3] = yy;
                p[4] = q00; p[5] = q01; p[6] = q10; p[7] = q11;
            }
        }
    }
    __syncthreads();

    if (tid < 128) {
        float s0[8], s1[8];
        #pragma unroll
        for (int e = 0; e < 8; e++) {
            s0[e] = Ps[tid * 8 + e];
            s1[e] = Ps[(128 + tid) * 8 + e];
        }
        float x6 = s0[0] + s1[0], x7 = s0[1] + s1[1];
        float xx = s0[2] + s1[2], yy = s0[3] + s1[3];
        float q00 = s0[4] + s1[4], q01 = s0[5] + s1[5];
        float q10 = s0[6] + s1[6], q11 = s0[7] + s1[7];
        float n2 = (q00 + q01) + (q10 + q11);
        float inv = 1.0f / n2;
        float* o = out + (size_t)(mbase + tid) * 9;
        o[0] = x6 * inv;                               // <X> wire 6
        o[1] = 0.0f;                                   // <Y> on a real state = 0
        o[2] = ((q00 + q01) - (q10 + q11)) * inv;      // <Z> wire 6
        o[3] = 2.0f * x7 * inv;                        // <X> wire 7
        o[4] = 0.0f;
        o[5] = ((q00 + q10) - (q01 + q11)) * inv;      // <Z> wire 7
        o[6] = xx * inv;                               // <XX>
        o[7] = yy * inv;                               // <YY>
        o[8] = ((q00 + q11) - (q01 + q10)) * inv;      // <ZZ>
    }
}

// ---------------- launch ----------------
extern "C" void kernel_launch(void* const* d_in, const int* in_sizes, int n_in,
                              void* d_out, int out_size) {
    const float* x = (const float*)d_in[0];
    const float* w = (const float*)d_in[1];
    if (n_in >= 2 && in_sizes[0] == NW) { const float* t = x; x = w; w = t; }
    float* out = (float*)d_out;

    cudaFuncSetAttribute(gemm_kernel, cudaFuncAttributeMaxDynamicSharedMemorySize, SMEM_TOTAL);

    build_u_kernel<<<8, 128>>>(w);
    split_u_kernel<<<32, 256>>>();
    gemm_kernel<<<BATCH / 128, 256, SMEM_TOTAL>>>(x, out);
}

// round 12
// speedup vs baseline: 2.5930x; 2.5930x over previous
#include <cuda_runtime.h>
#include <cuda_fp16.h>

#define DIM 256
#define NW 26
#define BATCH 32768
#define NJOBS 512            // 64-sample m-tiles
#define GRID 148

typedef unsigned long long ull;
typedef unsigned int u32;

// U image, fp16, already in the swizzled smem layout: row n (512B stride),
// 16B unit c holds k = c*8..c*8+7, stored at unit (c ^ (n&7)).
__device__ __align__(16) __half g_Uimg[DIM * DIM];

// ---------------- build_u: transposed circuit, one warp per basis row ----------------
// R1 layout (verified): lane L holds amps i = L*8+e. Wires 0-4 = lane bits
// (masks 16,8,4,2,1), wires 5,6,7 = reg bits (masks 4,2,1).
// Transpose: reverse gate order, t -> -t. Result: lane holds U[n][k], k = L*8+e.
template<int LM>
__device__ __forceinline__ void rot_cross8(float* r, float t, int lane) {
    float se = (lane & LM) ? t : -t;
    #pragma unroll
    for (int e = 0; e < 8; e++) {
        float p = __shfl_xor_sync(0xffffffffu, r[e], LM);
        r[e] = fmaf(se, p, r[e]);
    }
}
template<int M>
__device__ __forceinline__ void rot_reg8(float* r, float t) {
    #pragma unroll
    for (int e = 0; e < 8; e++) {
        if (e & M) continue;
        float a = r[e];
        r[e]     = fmaf(-t, r[e | M], a);
        r[e | M] = fmaf( t, a, r[e | M]);
    }
}

__global__ __launch_bounds__(128) void build_u_kernel(const float* __restrict__ w) {
    __shared__ float st[NW];                 // NEGATED tan(theta/2) -> transpose
    int tid = threadIdx.x;
    if (tid < NW) {
        float s, c;
        sincosf(0.5f * w[tid], &s, &c);
        st[tid] = -s / c;
    }
    __syncthreads();

    int lane = tid & 31;
    int n = blockIdx.x * 4 + (tid >> 5);     // basis row 0..255

    float r[8];
    #pragma unroll
    for (int e = 0; e < 8; e++) r[e] = (lane * 8 + e == n) ? 1.0f : 0.0f;

    // CZ parity mask over this lane's 8 amps (verified R1 formula)
    unsigned czm = 0;
    #pragma unroll
    for (int e = 0; e < 8; e++) {
        int i = (lane << 3) | e;
        int b0 = (i >> 7) & 1, b1 = (i >> 6) & 1;
        int rp = __popc(i & 63) & 1;
        czm |= (unsigned)((b0 & b1) ^ ((b0 ^ b1) & rp)) << e;
    }

    // transposed: trash RYs first, then layers 2,1,0 each as (CZ, RYs)
    rot_cross8<8>(r, st[25], lane);          // wire 1
    rot_cross8<16>(r, st[24], lane);         // wire 0
    #pragma unroll
    for (int l = 2; l >= 0; l--) {
        const int b = l * 8;
        #pragma unroll
        for (int e = 0; e < 8; e++) {
            unsigned sb = (czm << (31 - e)) & 0x80000000u;
            r[e] = __uint_as_float(__float_as_uint(r[e]) ^ sb);
        }
        rot_cross8<16>(r, st[b + 0], lane);  // wire 0
        rot_cross8<8>(r, st[b + 1], lane);   // wire 1
        rot_cross8<4>(r, st[b + 2], lane);   // wire 2
        rot_cross8<2>(r, st[b + 3], lane);   // wire 3
        rot_cross8<1>(r, st[b + 4], lane);   // wire 4
        rot_reg8<4>(r, st[b + 5]);           // wire 5
        rot_reg8<2>(r, st[b + 6]);           // wire 6
        rot_reg8<1>(r, st[b + 7]);           // wire 7
    }

    // pack 8 fp16 and store one swizzled 16B unit: unit c = lane, phys c^(n&7)
    __half2 h0 = __float22half2_rn(make_float2(r[0], r[1]));
    __half2 h1 = __float22half2_rn(make_float2(r[2], r[3]));
    __half2 h2 = __float22half2_rn(make_float2(r[4], r[5]));
    __half2 h3 = __float22half2_rn(make_float2(r[6], r[7]));
    uint4 val = make_uint4(*(u32*)&h0, *(u32*)&h1, *(u32*)&h2, *(u32*)&h3);
    char* dst = reinterpret_cast<char*>(g_Uimg) + n * 512 + ((lane ^ (n & 7)) << 4);
    *reinterpret_cast<uint4*>(dst) = val;
}

// ---------------- gemm: resident U, persistent CTAs, fused epilogue ----------------
// smem: [0,128K) U image; [128K, 192K) X fp16 double buffer (64 rows x 512B);
// [192K, 208K) partial forms [64 rows][8 nwarps][8].
#define U_OFF 0
#define X_OFF 131072
#define P_OFF 196608
#define SMEM_TOTAL 212992

#define LDMX4(r, addr) \
    asm volatile("ldmatrix.sync.aligned.m8n8.x4.shared.b16 {%0,%1,%2,%3}, [%4];" \
        : "=r"((r)[0]), "=r"((r)[1]), "=r"((r)[2]), "=r"((r)[3]) : "r"(addr))
#define MMA16816(d, a, b0_, b1_) \
    asm volatile("mma.sync.aligned.m16n8k16.row.col.f32.f16.f16.f32 " \
        "{%0,%1,%2,%3}, {%4,%5,%6,%7}, {%8,%9}, {%0,%1,%2,%3};" \
        : "+f"((d)[0]), "+f"((d)[1]), "+f"((d)[2]), "+f"((d)[3]) \
        : "r"((a)[0]), "r"((a)[1]), "r"((a)[2]), "r"((a)[3]), "r"(b0_), "r"(b1_))

__global__ __launch_bounds__(256, 1) void gemm_kernel(const float* __restrict__ x,
                                                      float* __restrict__ out) {
    extern __shared__ __align__(16) char smem[];
    u32 sb;
    asm("{ .reg .u64 t; cvta.to.shared.u64 t, %1; cvt.u32.u64 %0, t; }" : "=r"(sb) : "l"(smem));
    int tid = threadIdx.x, wid = tid >> 5, lane = tid & 31;
    int nw = wid;                                  // 8 warps: n-range = nw*32..+32, m-range 0..64
    int g = lane >> 3, ln8 = lane & 7;

    // load resident U image (128KB from L2)
    {
        const uint4* src = reinterpret_cast<const uint4*>(g_Uimg);
        uint4* dst = reinterpret_cast<uint4*>(smem + U_OFF);
        #pragma unroll
        for (int i = 0; i < 32; i++) dst[tid + i * 256] = src[tid + i * 256];
    }

    // X tile loader: 64 rows fp32 -> fp16 swizzled smem
    auto loadX = [&](int job, int buf) {
        const float4* xp = reinterpret_cast<const float4*>(x + (size_t)job * 64 * DIM);
        #pragma unroll
        for (int i = 0; i < 16; i++) {
            int idx = tid + i * 256;               // 0..4095 float4s
            int row = idx >> 6, kc4 = idx & 63;
            float4 v = xp[idx];
            __half2 h01 = __float22half2_rn(make_float2(v.x, v.y));
            __half2 h23 = __float22half2_rn(make_float2(v.z, v.w));
            u32 c = (u32)(kc4 >> 1);
            u32 addr = (u32)(X_OFF + buf * 32768 + row * 512) +
                       (((c ^ (u32)(row & 7)) << 4)) + ((u32)(kc4 & 1) << 3);
            *reinterpret_cast<ull*>(smem + addr) =
                ((ull)(*(u32*)&h23) << 32) | (*(u32*)&h01);
        }
    };

    int job = blockIdx.x;
    loadX(job, 0);
    __syncthreads();

    // frag address components (row&7 == ln8 for all frags -> constant swizzle)
    u32 raA = (u32)((g & 1) * 8 + ln8) * 512;      // + mt*16*512
    u32 uA = (u32)(g >> 1);
    u32 raB = (u32)(nw * 32 + (g >> 1) * 8 + ln8) * 512;   // + nt16*16*512
    u32 uB = (u32)(g & 1);
    u32 swl = (u32)ln8;

    float* P = reinterpret_cast<float*>(smem + P_OFF);
    float sgn = (lane & 1) ? 1.0f : -1.0f;

    int jidx = 0;
    for (;;) {
        int cur = jidx & 1;
        u32 xbase = sb + (u32)(X_OFF + cur * 32768);
        u32 ubase = sb + U_OFF;

        float d[4][4][4];                          // [mt 0..3][nt8 0..3][reg]
        #pragma unroll
        for (int a = 0; a < 4; a++)
            #pragma unroll
            for (int b = 0; b < 4; b++)
                #pragma unroll
                for (int e = 0; e < 4; e++) d[a][b][e] = 0.0f;

        #pragma unroll 4
        for (int s = 0; s < 16; s++) {
            u32 offA = (((2 * (u32)s + uA) ^ swl) << 4);
            u32 offB = (((2 * (u32)s + uB) ^ swl) << 4);
            u32 b0[4], b1[4];
            LDMX4(b0, ubase + raB + offB);                 // n-tiles 0,1 (nt16=0)
            LDMX4(b1, ubase + raB + 16 * 512 + offB);      // n-tiles 2,3
            #pragma unroll
            for (int mt = 0; mt < 4; mt++) {
                u32 a[4];
                LDMX4(a, xbase + raA + (u32)(mt * 16) * 512 + offA);
                MMA16816(d[mt][0], a, b0[0], b0[1]);
                MMA16816(d[mt][1], a, b0[2], b0[3]);
                MMA16816(d[mt][2], a, b1[0], b1[1]);
                MMA16816(d[mt][3], a, b1[2], b1[3]);
            }
        }

        // prefetch next job's X into the other buffer (hidden behind epilogue)
        int nj = job + GRID;
        if (nj < NJOBS) loadX(nj, 1 - cur);

        // ---- epilogue: per-row forms (conventions verified in R11) ----
        // cols: n = nw*32 + nt8*8 + (lane&3)*2 + reg; rows: m = mt*16 + h*8 + (lane>>2)
        #pragma unroll
        for (int mt = 0; mt < 4; mt++) {
            #pragma unroll
            for (int h = 0; h < 2; h++) {
                float x6 = 0, x7 = 0, xx = 0, yy = 0, qa = 0, qb = 0;
                #pragma unroll
                for (int nt = 0; nt < 4; nt++) {
                    float v0 = d[mt][nt][h * 2], v1 = d[mt][nt][h * 2 + 1];
                    float p0 = __shfl_xor_sync(0xffffffffu, v0, 1);
                    float p1 = __shfl_xor_sync(0xffffffffu, v1, 1);
                    x7 = fmaf(v0, v1, x7);
                    x6 = fmaf(v0, p0, x6); x6 = fmaf(v1, p1, x6);
                    xx = fmaf(v0, p1, xx); xx = fmaf(v1, p0, xx);
                    yy = fmaf(sgn * v0, p1, yy); yy = fmaf(-sgn * v1, p0, yy);
                    qa = fmaf(v0, v0, qa); qb = fmaf(v1, v1, qb);
                }
                x6 += __shfl_xor_sync(0xffffffffu, x6, 1); x6 += __shfl_xor_sync(0xffffffffu, x6, 2);
                x7 += __shfl_xor_sync(0xffffffffu, x7, 1); x7 += __shfl_xor_sync(0xffffffffu, x7, 2);
                xx += __shfl_xor_sync(0xffffffffu, xx, 1); xx += __shfl_xor_sync(0xffffffffu, xx, 2);
                yy += __shfl_xor_sync(0xffffffffu, yy, 1); yy += __shfl_xor_sync(0xffffffffu, yy, 2);
                qa += __shfl_xor_sync(0xffffffffu, qa, 2);
                qb += __shfl_xor_sync(0xffffffffu, qb, 2);
                float pqa = __shfl_xor_sync(0xffffffffu, qa, 1);
                float pqb = __shfl_xor_sync(0xffffffffu, qb, 1);
                float q0, q1, q2, q3;
                if (!(lane & 1)) { q0 = qa; q1 = qb; q2 = pqa; q3 = pqb; }
                else             { q0 = pqa; q1 = pqb; q2 = qa; q3 = qb; }
                if ((lane & 3) == 0) {
                    int row = mt * 16 + h * 8 + (lane >> 2);
                    float* p = P + (row * 8 + nw) * 8;
                    p[0] = x6; p[1] = x7; p[2] = xx; p[3] = yy;
                    p[4] = q0; p[5] = q1; p[6] = q2; p[7] = q3;
                }
            }
        }
        __syncthreads();

        if (tid < 64) {
            float acc[8];
            #pragma unroll
            for (int f = 0; f < 8; f++) acc[f] = 0.0f;
            #pragma unroll
            for (int nv = 0; nv < 8; nv++) {
                const float* p = P + (tid * 8 + nv) * 8;
                #pragma unroll
                for (int f = 0; f < 8; f++) acc[f] += p[f];
            }
            float n2 = (acc[4] + acc[5]) + (acc[6] + acc[7]);
            float inv = 1.0f / n2;
            float* o = out + (size_t)(job * 64 + tid) * 9;
            o[0] = acc[0] * inv;                                // <X> wire 6
            o[1] = 0.0f;                                        // <Y> real state = 0
            o[2] = ((acc[4] + acc[5]) - (acc[6] + acc[7])) * inv;
            o[3] = 2.0f * acc[1] * inv;                         // <X> wire 7
            o[4] = 0.0f;
            o[5] = ((acc[4] + acc[6]) - (acc[5] + acc[7])) * inv;
            o[6] = acc[2] * inv;                                // <XX>
            o[7] = acc[3] * inv;                                // <YY>
            o[8] = ((acc[4] + acc[7]) - (acc[5] + acc[6])) * inv;
        }

        job = nj; jidx++;
        if (job >= NJOBS) break;
        __syncthreads();                            // protect P + X buffer
    }
}

// ---------------- launch ----------------
extern "C" void kernel_launch(void* const* d_in, const int* in_sizes, int n_in,
                              void* d_out, int out_size) {
    const float* x = (const float*)d_in[0];
    const float* w = (const float*)d_in[1];
    if (n_in >= 2 && in_sizes[0] == NW) { const float* t = x; x = w; w = t; }
    float* out = (float*)d_out;

    cudaFuncSetAttribute(gemm_kernel, cudaFuncAttributeMaxDynamicSharedMemorySize, SMEM_TOTAL);

    build_u_kernel<<<64, 128>>>(w);
    gemm_kernel<<<GRID, 256, SMEM_TOTAL>>>(x, out);
}